// round 11
// baseline (speedup 1.0000x reference)
#include <cuda_runtime.h>
#include <cuda_bf16.h>

// Scratch (allocation-free rule: __device__ globals, zero-init at load).
// g_acc[0..4]=pred hist, [5..9]=target hist, [10]=sum (t-p)^2.
// g_tile = dynamic work-stealing tile counter.
// Invariant: all zero at entry to kernel_launch (finalize resets them).
static __device__ unsigned int g_acc[11];
static __device__ unsigned int g_tile;

#define QWK_THREADS 128
#define TILE_ROWS   512
#define TILE_BYTES  (TILE_ROWS * 20)          // 10240 B per tile
#define TILE_F4     (TILE_BYTES / 16)         // 640 float4 = 5 per thread
#define GROUPS_PER_TILE (TILE_ROWS / 4)       // 128 = one group per thread

__device__ __forceinline__ void cp16(void* dst_smem, const void* src) {
    unsigned int saddr = (unsigned int)__cvta_generic_to_shared(dst_smem);
    asm volatile("cp.async.cg.shared.global [%0], [%1], 16;\n" :: "r"(saddr), "l"(src));
}
#define CP_COMMIT() asm volatile("cp.async.commit_group;\n" ::: "memory")
#define CP_WAIT1()  asm volatile("cp.async.wait_group 1;\n" ::: "memory")
#define CP_WAIT0()  asm volatile("cp.async.wait_group 0;\n" ::: "memory")

__device__ __forceinline__ int argmax5(float v0, float v1, float v2, float v3, float v4) {
    // first-max semantics (strict >) to match jnp.argmax
    int bi = 0; float bv = v0;
    if (v1 > bv) { bv = v1; bi = 1; }
    if (v2 > bv) { bv = v2; bi = 2; }
    if (v3 > bv) { bv = v3; bi = 3; }
    if (v4 > bv) { bv = v4; bi = 4; }
    return bi;
}

__global__ void __launch_bounds__(QWK_THREADS, 8) qwk_main(
    const float* __restrict__ logits,
    const int4* __restrict__ targets4,
    const int*  __restrict__ targets,
    int n, int ntiles)
{
    __shared__ __align__(16) float s_buf[2][TILE_BYTES / 4];
    __shared__ int s_T[2];
    const int t = threadIdx.x;

    // Register accumulators: two packed 5x12-bit hists + d^2 sum.
    // Rows/thread <= ~60 << 4095 lane cap.
    unsigned long long pred_pack = 0ull;
    unsigned long long tgt_pack  = 0ull;
    unsigned int d2 = 0u;

    // Tail rows (n % 512) — dead at runtime (8e6 = 512*15625 exactly).
    if (blockIdx.x == 0 && t == 0) {
        for (int r = ntiles * TILE_ROWS; r < n; r++) {
            const float* L = logits + (size_t)r * 5;
            int p = argmax5(L[0], L[1], L[2], L[3], L[4]);
            int tv = targets[r];
            pred_pack += 1ull << (12 * p);
            tgt_pack  += 1ull << (12 * tv);
            int d = tv - p;
            d2 += (unsigned int)(d * d);
        }
    }

    // Dynamic work stealing: grab two tiles to prime the double buffer.
    if (t == 0) {
        s_T[0] = (int)atomicAdd(&g_tile, 1u);
        s_T[1] = (int)atomicAdd(&g_tile, 1u);
    }
    __syncthreads();
    int Tq[2] = { s_T[0], s_T[1] };

    #pragma unroll
    for (int k = 0; k < 2; k++) {
        if (Tq[k] < ntiles) {
            const float* src = logits + (size_t)Tq[k] * (TILE_BYTES / 4);
            #pragma unroll
            for (int j = 0; j < 5; j++)
                cp16(&s_buf[k][ (t + j * QWK_THREADS) * 4 ],
                     src + (t + j * QWK_THREADS) * 4);
        }
        CP_COMMIT();
    }

    int cur = 0;
    while (Tq[cur] < ntiles) {
        const int T = Tq[cur];

        CP_WAIT1();          // this tile's copy complete (<=1 younger group pending)
        __syncthreads();

        // Process: thread t -> 4 consecutive rows at smem bytes t*80..t*80+79.
        // 5x LDS.128, lane stride 20 words: conflict-free (all 32 banks/phase).
        const float4* rp = (const float4*)(s_buf[cur] + t * 20);
        float4 a = rp[0], b = rp[1], c = rp[2], d = rp[3], e = rp[4];
        int4 tg = __ldg(targets4 + (size_t)T * GROUPS_PER_TILE + t);

        int p0 = argmax5(a.x, a.y, a.z, a.w, b.x);
        int p1 = argmax5(b.y, b.z, b.w, c.x, c.y);
        int p2 = argmax5(c.z, c.w, d.x, d.y, d.z);
        int p3 = argmax5(d.w, e.x, e.y, e.z, e.w);

        pred_pack += (1ull << (12 * p0)) + (1ull << (12 * p1))
                   + (1ull << (12 * p2)) + (1ull << (12 * p3));
        tgt_pack  += (1ull << (12 * tg.x)) + (1ull << (12 * tg.y))
                   + (1ull << (12 * tg.z)) + (1ull << (12 * tg.w));
        int e0 = tg.x - p0, e1 = tg.y - p1, e2 = tg.z - p2, e3 = tg.w - p3;
        d2 += (unsigned int)(e0*e0 + e1*e1 + e2*e2 + e3*e3);

        // Steal the next tile (piggybacks on the existing sync below).
        if (t == 0) s_T[cur] = (int)atomicAdd(&g_tile, 1u);
        __syncthreads();     // buf[cur] fully read + s_T[cur] visible

        const int Tn = s_T[cur];
        Tq[cur] = Tn;
        if (Tn < ntiles) {
            const float* src = logits + (size_t)Tn * (TILE_BYTES / 4);
            #pragma unroll
            for (int j = 0; j < 5; j++)
                cp16(&s_buf[cur][ (t + j * QWK_THREADS) * 4 ],
                     src + (t + j * QWK_THREADS) * 4);
        }
        CP_COMMIT();         // empty groups complete immediately — keeps count consistent
        cur ^= 1;
    }
    CP_WAIT0();
    __syncthreads();

    // Block reduction: unpack 12-bit lanes -> 11 u32, warp-reduce, one shared
    // atomic per warp, then one global atomic per counter per block.
    unsigned int* s_red = (unsigned int*)s_buf;   // buffers idle now
    unsigned int v[11];
    #pragma unroll
    for (int i = 0; i < 5; i++) {
        v[i]     = (unsigned int)((pred_pack >> (12 * i)) & 0xFFFull);
        v[5 + i] = (unsigned int)((tgt_pack  >> (12 * i)) & 0xFFFull);
    }
    v[10] = d2;
    if (t < 11) s_red[t] = 0u;
    __syncthreads();
    #pragma unroll
    for (int i = 0; i < 11; i++) {
        unsigned int r = __reduce_add_sync(0xffffffffu, v[i]);
        if ((t & 31) == 0 && r) atomicAdd(&s_red[i], r);
    }
    __syncthreads();
    if (t < 11) {
        unsigned int r = s_red[t];
        if (r) atomicAdd(&g_acc[t], r);
    }
}

__global__ void qwk_finalize(int n, float* __restrict__ out) {
    if (threadIdx.x == 0) {
        double pred_h[5], tgt_h[5];
        #pragma unroll
        for (int i = 0; i < 5; i++) {
            pred_h[i] = (double)g_acc[i];
            tgt_h[i]  = (double)g_acc[5 + i];
        }
        double num = (double)g_acc[10] * (1.0 / 16.0);
        double inv_tot = 1.0 / (double)n;      // the only FP64 divide
        double den_s = 0.0;
        #pragma unroll
        for (int i = 0; i < 5; i++) {
            #pragma unroll
            for (int j = 0; j < 5; j++) {
                double w = (double)((i - j) * (i - j));
                den_s += w * (tgt_h[i] * pred_h[j]);   // pure DFMA chain
            }
        }
        double den = den_s * (1.0 / 16.0) * inv_tot;
        // reference returns 1 - qwk = num / (den + 1e-6)
        out[0] = (float)(num / (den + 1e-6));
        // restore invariants for next call/replay
        #pragma unroll
        for (int i = 0; i < 11; i++) g_acc[i] = 0u;
        g_tile = 0u;
    }
}

extern "C" void kernel_launch(void* const* d_in, const int* in_sizes, int n_in,
                              void* d_out, int out_size) {
    const float* logits  = (const float*)d_in[0];
    const int*   targets = (const int*)d_in[1];
    const int n = in_sizes[1];
    const int ntiles = n / TILE_ROWS;

    int blocks = ntiles;
    if (blocks < 1) blocks = 1;
    if (blocks > 1184) blocks = 1184;   // 148 SMs x 8 blocks resident (one wave)
    qwk_main<<<blocks, QWK_THREADS>>>(logits, (const int4*)targets, targets,
                                      n, ntiles);
    qwk_finalize<<<1, 32>>>(n, (float*)d_out);
}

// round 12
// speedup vs baseline: 1.0033x; 1.0033x over previous
#include <cuda_runtime.h>
#include <cuda_bf16.h>

// Scratch (allocation-free rule: __device__ globals, zero-init at load).
// g_acc[0..4]=pred hist, [5..9]=target hist, [10]=sum (t-p)^2.
// g_tile = dynamic work-stealing tile counter.
// Invariant: all zero at entry to kernel_launch (finalize resets them).
static __device__ unsigned int g_acc[11];
static __device__ unsigned int g_tile;

#define QWK_THREADS 128
#define TILE_ROWS   512
#define TILE_BYTES  (TILE_ROWS * 20)          // 10240 B per tile
#define TILE_F4     (TILE_BYTES / 16)         // 640 float4 = 5 per thread
#define GROUPS_PER_TILE (TILE_ROWS / 4)       // 128 = one group per thread

__device__ __forceinline__ void cp16(void* dst_smem, const void* src) {
    unsigned int saddr = (unsigned int)__cvta_generic_to_shared(dst_smem);
    asm volatile("cp.async.cg.shared.global [%0], [%1], 16;\n" :: "r"(saddr), "l"(src));
}
#define CP_COMMIT() asm volatile("cp.async.commit_group;\n" ::: "memory")
#define CP_WAIT1()  asm volatile("cp.async.wait_group 1;\n" ::: "memory")
#define CP_WAIT0()  asm volatile("cp.async.wait_group 0;\n" ::: "memory")

__device__ __forceinline__ int argmax5(float v0, float v1, float v2, float v3, float v4) {
    // first-max semantics (strict >) to match jnp.argmax
    int bi = 0; float bv = v0;
    if (v1 > bv) { bv = v1; bi = 1; }
    if (v2 > bv) { bv = v2; bi = 2; }
    if (v3 > bv) { bv = v3; bi = 3; }
    if (v4 > bv) { bv = v4; bi = 4; }
    return bi;
}

__global__ void __launch_bounds__(QWK_THREADS, 8) qwk_main(
    const float* __restrict__ logits,
    const int4* __restrict__ targets4,
    const int*  __restrict__ targets,
    int n, int ntiles)
{
    __shared__ __align__(16) float s_buf[2][TILE_BYTES / 4];
    __shared__ int s_T[2];
    const int t = threadIdx.x;

    // Register accumulators: two packed 5x12-bit hists + d^2 sum.
    // Rows/thread <= ~60 << 4095 lane cap.
    unsigned long long pred_pack = 0ull;
    unsigned long long tgt_pack  = 0ull;
    unsigned int d2 = 0u;

    // Tail rows (n % 512) — dead at runtime (8e6 = 512*15625 exactly).
    if (blockIdx.x == 0 && t == 0) {
        for (int r = ntiles * TILE_ROWS; r < n; r++) {
            const float* L = logits + (size_t)r * 5;
            int p = argmax5(L[0], L[1], L[2], L[3], L[4]);
            int tv = targets[r];
            pred_pack += 1ull << (12 * p);
            tgt_pack  += 1ull << (12 * tv);
            int d = tv - p;
            d2 += (unsigned int)(d * d);
        }
    }

    // Dynamic work stealing: grab two tiles to prime the double buffer.
    if (t == 0) {
        s_T[0] = (int)atomicAdd(&g_tile, 1u);
        s_T[1] = (int)atomicAdd(&g_tile, 1u);
    }
    __syncthreads();
    int Tq[2] = { s_T[0], s_T[1] };

    #pragma unroll
    for (int k = 0; k < 2; k++) {
        if (Tq[k] < ntiles) {
            const float* src = logits + (size_t)Tq[k] * (TILE_BYTES / 4);
            #pragma unroll
            for (int j = 0; j < 5; j++)
                cp16(&s_buf[k][ (t + j * QWK_THREADS) * 4 ],
                     src + (t + j * QWK_THREADS) * 4);
        }
        CP_COMMIT();
    }

    int cur = 0;
    while (Tq[cur] < ntiles) {
        const int T = Tq[cur];

        CP_WAIT1();          // this tile's copy complete (<=1 younger group pending)
        __syncthreads();

        // Steal the NEXT tile for this slot *before* processing: the ~318-cyc
        // ATOMG return latency overlaps the LDS/argmax work below, and the
        // result is consumed only after the post-process barrier. (R10 issued
        // this after processing — exposing the full latency on the critical
        // path every iteration.)
        if (t == 0) s_T[cur] = (int)atomicAdd(&g_tile, 1u);

        // Process: thread t -> 4 consecutive rows at smem bytes t*80..t*80+79.
        // 5x LDS.128, lane stride 20 words: conflict-free (all 32 banks/phase).
        const float4* rp = (const float4*)(s_buf[cur] + t * 20);
        float4 a = rp[0], b = rp[1], c = rp[2], d = rp[3], e = rp[4];
        int4 tg = __ldg(targets4 + (size_t)T * GROUPS_PER_TILE + t);

        int p0 = argmax5(a.x, a.y, a.z, a.w, b.x);
        int p1 = argmax5(b.y, b.z, b.w, c.x, c.y);
        int p2 = argmax5(c.z, c.w, d.x, d.y, d.z);
        int p3 = argmax5(d.w, e.x, e.y, e.z, e.w);

        pred_pack += (1ull << (12 * p0)) + (1ull << (12 * p1))
                   + (1ull << (12 * p2)) + (1ull << (12 * p3));
        tgt_pack  += (1ull << (12 * tg.x)) + (1ull << (12 * tg.y))
                   + (1ull << (12 * tg.z)) + (1ull << (12 * tg.w));
        int e0 = tg.x - p0, e1 = tg.y - p1, e2 = tg.z - p2, e3 = tg.w - p3;
        d2 += (unsigned int)(e0*e0 + e1*e1 + e2*e2 + e3*e3);

        __syncthreads();     // buf[cur] fully read + s_T[cur] visible

        const int Tn = s_T[cur];
        Tq[cur] = Tn;
        if (Tn < ntiles) {
            const float* src = logits + (size_t)Tn * (TILE_BYTES / 4);
            #pragma unroll
            for (int j = 0; j < 5; j++)
                cp16(&s_buf[cur][ (t + j * QWK_THREADS) * 4 ],
                     src + (t + j * QWK_THREADS) * 4);
        }
        CP_COMMIT();         // empty groups complete immediately — keeps count consistent
        cur ^= 1;
    }
    CP_WAIT0();
    __syncthreads();

    // Block reduction: unpack 12-bit lanes -> 11 u32, warp-reduce, one shared
    // atomic per warp, then one global atomic per counter per block.
    unsigned int* s_red = (unsigned int*)s_buf;   // buffers idle now
    unsigned int v[11];
    #pragma unroll
    for (int i = 0; i < 5; i++) {
        v[i]     = (unsigned int)((pred_pack >> (12 * i)) & 0xFFFull);
        v[5 + i] = (unsigned int)((tgt_pack  >> (12 * i)) & 0xFFFull);
    }
    v[10] = d2;
    if (t < 11) s_red[t] = 0u;
    __syncthreads();
    #pragma unroll
    for (int i = 0; i < 11; i++) {
        unsigned int r = __reduce_add_sync(0xffffffffu, v[i]);
        if ((t & 31) == 0 && r) atomicAdd(&s_red[i], r);
    }
    __syncthreads();
    if (t < 11) {
        unsigned int r = s_red[t];
        if (r) atomicAdd(&g_acc[t], r);
    }
}

__global__ void qwk_finalize(int n, float* __restrict__ out) {
    if (threadIdx.x == 0) {
        double pred_h[5], tgt_h[5];
        #pragma unroll
        for (int i = 0; i < 5; i++) {
            pred_h[i] = (double)g_acc[i];
            tgt_h[i]  = (double)g_acc[5 + i];
        }
        double num = (double)g_acc[10] * (1.0 / 16.0);
        double inv_tot = 1.0 / (double)n;      // the only FP64 divide
        double den_s = 0.0;
        #pragma unroll
        for (int i = 0; i < 5; i++) {
            #pragma unroll
            for (int j = 0; j < 5; j++) {
                double w = (double)((i - j) * (i - j));
                den_s += w * (tgt_h[i] * pred_h[j]);   // pure DFMA chain
            }
        }
        double den = den_s * (1.0 / 16.0) * inv_tot;
        // reference returns 1 - qwk = num / (den + 1e-6)
        out[0] = (float)(num / (den + 1e-6));
        // restore invariants for next call/replay
        #pragma unroll
        for (int i = 0; i < 11; i++) g_acc[i] = 0u;
        g_tile = 0u;
    }
}

extern "C" void kernel_launch(void* const* d_in, const int* in_sizes, int n_in,
                              void* d_out, int out_size) {
    const float* logits  = (const float*)d_in[0];
    const int*   targets = (const int*)d_in[1];
    const int n = in_sizes[1];
    const int ntiles = n / TILE_ROWS;

    int blocks = ntiles;
    if (blocks < 1) blocks = 1;
    if (blocks > 1184) blocks = 1184;   // 148 SMs x 8 blocks resident (one wave)
    qwk_main<<<blocks, QWK_THREADS>>>(logits, (const int4*)targets, targets,
                                      n, ntiles);
    qwk_finalize<<<1, 32>>>(n, (float*)d_out);
}

// round 14
// speedup vs baseline: 1.1211x; 1.1174x over previous
#include <cuda_runtime.h>
#include <cuda_bf16.h>

// Scratch (allocation-free rule: __device__ globals, zero-init at load).
// g_acc[0..4]=pred hist, [5..9]=target hist, [10]=sum (t-p)^2.
// Invariant: g_acc == 0 at entry to kernel_launch (finalize resets it).
static __device__ unsigned int g_acc[11];

#define QWK_THREADS 128
#define TILE_ROWS   512
#define TILE_BYTES  (TILE_ROWS * 20)          // 10240 B per tile
#define TILE_F4     (TILE_BYTES / 16)         // 640 float4 = 5 per thread
#define GROUPS_PER_TILE (TILE_ROWS / 4)       // 128 = one group per thread

__device__ __forceinline__ void cp16(void* dst_smem, const void* src) {
    unsigned int saddr = (unsigned int)__cvta_generic_to_shared(dst_smem);
    asm volatile("cp.async.cg.shared.global [%0], [%1], 16;\n" :: "r"(saddr), "l"(src));
}
#define CP_COMMIT() asm volatile("cp.async.commit_group;\n" ::: "memory")
#define CP_WAIT1()  asm volatile("cp.async.wait_group 1;\n" ::: "memory")
#define CP_WAIT0()  asm volatile("cp.async.wait_group 0;\n" ::: "memory")

__device__ __forceinline__ int argmax5(float v0, float v1, float v2, float v3, float v4) {
    // first-max semantics (strict >) to match jnp.argmax
    int bi = 0; float bv = v0;
    if (v1 > bv) { bv = v1; bi = 1; }
    if (v2 > bv) { bv = v2; bi = 2; }
    if (v3 > bv) { bv = v3; bi = 3; }
    if (v4 > bv) { bv = v4; bi = 4; }
    return bi;
}

__global__ void __launch_bounds__(QWK_THREADS, 8) qwk_main(
    const float* __restrict__ logits,
    const int4* __restrict__ targets4,
    const int*  __restrict__ targets,
    int n, int ntiles)
{
    __shared__ __align__(16) float s_buf[2][TILE_BYTES / 4];
    const int t = threadIdx.x;

    // Register accumulators: two packed 5x12-bit hists + d^2 sum.
    // Rows/thread <= ~60 << 4095 lane cap.
    unsigned long long pred_pack = 0ull;
    unsigned long long tgt_pack  = 0ull;
    unsigned int d2 = 0u;

    // Tail rows (n % 512) — dead at runtime (8e6 = 512*15625 exactly).
    if (blockIdx.x == 0 && t == 0) {
        for (int r = ntiles * TILE_ROWS; r < n; r++) {
            const float* L = logits + (size_t)r * 5;
            int p = argmax5(L[0], L[1], L[2], L[3], L[4]);
            int tv = targets[r];
            pred_pack += 1ull << (12 * p);
            tgt_pack  += 1ull << (12 * tv);
            int d = tv - p;
            d2 += (unsigned int)(d * d);
        }
    }

    // Static strided tiles: T_k = blockIdx.x + k*gridDim.x (one wave; per-SM
    // tile totals differ by ~1%, so no dynamic scheduling needed).
    const int grid = gridDim.x;
    const int nmine = (ntiles > blockIdx.x)
                        ? (ntiles - blockIdx.x + grid - 1) / grid : 0;

    // Prefetch k=0 and k=1 (identity layout: contiguous gmem -> contiguous smem).
    #pragma unroll
    for (int k = 0; k < 2; k++) {
        if (k < nmine) {
            const float* src = logits + ((size_t)blockIdx.x + (size_t)k * grid) * (TILE_BYTES / 4);
            #pragma unroll
            for (int j = 0; j < 5; j++)
                cp16(&s_buf[k][ (t + j * QWK_THREADS) * 4 ],
                     src + (t + j * QWK_THREADS) * 4);
        }
        CP_COMMIT();
    }

    for (int k = 0; k < nmine; k++) {
        const int cur = k & 1;
        const long long T = (long long)blockIdx.x + (long long)k * grid;

        // Hoisted targets load: issue the LDG *before* waiting on the tile
        // copy, so its ~600-cyc latency overlaps CP_WAIT1 + barrier instead of
        // landing inside the process phase. Consumed strictly after the sync.
        int4 tg = __ldg(targets4 + T * GROUPS_PER_TILE + t);

        CP_WAIT1();          // tile k's copy complete (<=1 younger group pending)
        __syncthreads();

        // Process: thread t -> 4 consecutive rows at smem bytes t*80..t*80+79.
        // 5x LDS.128, lane stride 20 words: conflict-free (all 32 banks/phase).
        const float4* rp = (const float4*)(s_buf[cur] + t * 20);
        float4 a = rp[0], b = rp[1], c = rp[2], d = rp[3], e = rp[4];

        int p0 = argmax5(a.x, a.y, a.z, a.w, b.x);
        int p1 = argmax5(b.y, b.z, b.w, c.x, c.y);
        int p2 = argmax5(c.z, c.w, d.x, d.y, d.z);
        int p3 = argmax5(d.w, e.x, e.y, e.z, e.w);

        pred_pack += (1ull << (12 * p0)) + (1ull << (12 * p1))
                   + (1ull << (12 * p2)) + (1ull << (12 * p3));
        tgt_pack  += (1ull << (12 * tg.x)) + (1ull << (12 * tg.y))
                   + (1ull << (12 * tg.z)) + (1ull << (12 * tg.w));
        int e0 = tg.x - p0, e1 = tg.y - p1, e2 = tg.z - p2, e3 = tg.w - p3;
        d2 += (unsigned int)(e0*e0 + e1*e1 + e2*e2 + e3*e3);

        __syncthreads();     // all threads done reading buf[cur]

        // Prefetch tile k+2 into the buffer just freed.
        if (k + 2 < nmine) {
            const float* src = logits + ((size_t)blockIdx.x + (size_t)(k + 2) * grid) * (TILE_BYTES / 4);
            #pragma unroll
            for (int j = 0; j < 5; j++)
                cp16(&s_buf[cur][ (t + j * QWK_THREADS) * 4 ],
                     src + (t + j * QWK_THREADS) * 4);
        }
        CP_COMMIT();         // empty groups complete immediately — keeps count consistent
    }
    CP_WAIT0();
    __syncthreads();

    // Block reduction: unpack 12-bit lanes -> 11 u32, warp-reduce, one shared
    // atomic per warp, then one global atomic per counter per block.
    unsigned int* s_red = (unsigned int*)s_buf;   // buffers idle now
    unsigned int v[11];
    #pragma unroll
    for (int i = 0; i < 5; i++) {
        v[i]     = (unsigned int)((pred_pack >> (12 * i)) & 0xFFFull);
        v[5 + i] = (unsigned int)((tgt_pack  >> (12 * i)) & 0xFFFull);
    }
    v[10] = d2;
    if (t < 11) s_red[t] = 0u;
    __syncthreads();
    #pragma unroll
    for (int i = 0; i < 11; i++) {
        unsigned int r = __reduce_add_sync(0xffffffffu, v[i]);
        if ((t & 31) == 0 && r) atomicAdd(&s_red[i], r);
    }
    __syncthreads();
    if (t < 11) {
        unsigned int r = s_red[t];
        if (r) atomicAdd(&g_acc[t], r);
    }
}

__global__ void qwk_finalize(int n, float* __restrict__ out) {
    if (threadIdx.x == 0) {
        double pred_h[5], tgt_h[5];
        #pragma unroll
        for (int i = 0; i < 5; i++) {
            pred_h[i] = (double)g_acc[i];
            tgt_h[i]  = (double)g_acc[5 + i];
        }
        double num = (double)g_acc[10] * (1.0 / 16.0);
        double inv_tot = 1.0 / (double)n;      // the only FP64 divide
        double den_s = 0.0;
        #pragma unroll
        for (int i = 0; i < 5; i++) {
            #pragma unroll
            for (int j = 0; j < 5; j++) {
                double w = (double)((i - j) * (i - j));
                den_s += w * (tgt_h[i] * pred_h[j]);   // pure DFMA chain
            }
        }
        double den = den_s * (1.0 / 16.0) * inv_tot;
        // reference returns 1 - qwk = num / (den + 1e-6)
        out[0] = (float)(num / (den + 1e-6));
        // restore invariant for next call/replay
        #pragma unroll
        for (int i = 0; i < 11; i++) g_acc[i] = 0u;
    }
}

extern "C" void kernel_launch(void* const* d_in, const int* in_sizes, int n_in,
                              void* d_out, int out_size) {
    const float* logits  = (const float*)d_in[0];
    const int*   targets = (const int*)d_in[1];
    const int n = in_sizes[1];
    const int ntiles = n / TILE_ROWS;

    int blocks = ntiles;
    if (blocks < 1) blocks = 1;
    if (blocks > 1184) blocks = 1184;   // 148 SMs x 8 blocks resident (one wave)
    qwk_main<<<blocks, QWK_THREADS>>>(logits, (const int4*)targets, targets,
                                      n, ntiles);
    qwk_finalize<<<1, 32>>>(n, (float*)d_out);
}